// round 2
// baseline (speedup 1.0000x reference)
#include <cuda_runtime.h>
#include <cuda_bf16.h>

// ---------------------------------------------------------------------------
// SimpleVQVAEEncoder: conv(8x8 s4 p2)+relu -> conv(6x6 s3 p2)+relu ->
// conv(4x4 s1 p0) -> nearest-codebook argmin -> one-hot [B,512,169]
// Inputs (metadata order): x, w1, b1, w2, b2, w3, b3, codebook
// ---------------------------------------------------------------------------

#define B_       128
#define H1OUT    48
#define H2OUT    16
#define H3OUT    13
#define HW3      (H3OUT*H3OUT)     // 169
#define NROWS    (B_*HW3)          // 21632
#define NEMB     512
#define EMB      64

// scratch (device globals: allocation-free rule)
__device__ __align__(16) float g_z1[B_*64*H1OUT*H1OUT];     // 75.5 MB
__device__ __align__(16) float g_z2[B_*128*H2OUT*H2OUT];    // 16.8 MB
__device__ __align__(16) float g_z3t[NROWS*EMB];            // 5.5 MB, [row][c]
__device__ int g_idx[NROWS];

// ---------------------------------------------------------------------------
// conv1: x[128,3,192,192] * w1[64,3,8,8] s4 p2 -> relu -> g_z1[128,64,48,48]
// block: 256 thr, computes (b, 8x8 spatial tile, all 64 oc); thread: 4oc x 4sp
// smem: weights transposed [k=192][oc=64] (pad 68), x patch 3x36x36
// ---------------------------------------------------------------------------
#define C1_WPAD 68
#define C1_SMEM ((192*C1_WPAD + 3*36*36)*4)

__global__ __launch_bounds__(256) void conv1_kernel(
    const float* __restrict__ x, const float* __restrict__ w1,
    const float* __restrict__ b1)
{
    extern __shared__ float sm[];
    float* w_s = sm;                       // 192*68
    float* x_s = sm + 192*C1_WPAD;         // 3*36*36

    const int tile = blockIdx.x;           // 0..35
    const int b    = blockIdx.y;
    const int oh0  = (tile / 6) * 8;
    const int ow0  = (tile % 6) * 8;
    const int ih0  = oh0*4 - 2;
    const int iw0  = ow0*4 - 2;
    const int t    = threadIdx.x;

    for (int idx = t; idx < 64*192; idx += 256) {
        int oc = idx / 192, k = idx % 192;
        w_s[k*C1_WPAD + oc] = w1[idx];
    }
    for (int idx = t; idx < 3*36*36; idx += 256) {
        int ci = idx / 1296, rem = idx % 1296;
        int py = rem / 36,  px = rem % 36;
        int ih = ih0 + py,  iw = iw0 + px;
        float v = 0.f;
        if (ih >= 0 && ih < 192 && iw >= 0 && iw < 192)
            v = x[((b*3 + ci)*192 + ih)*192 + iw];
        x_s[idx] = v;
    }
    __syncthreads();

    const int oc0 = (t >> 4) * 4;
    const int sg  = t & 15;
    const int sy  = sg >> 1;
    const int sx0 = (sg & 1) * 4;

    float acc[4][4];
    #pragma unroll
    for (int i = 0; i < 4; i++)
        #pragma unroll
        for (int j = 0; j < 4; j++) acc[i][j] = 0.f;

    for (int ci = 0; ci < 3; ci++) {
        #pragma unroll 2
        for (int kh = 0; kh < 8; kh++) {
            const float* xr = &x_s[(ci*36 + sy*4 + kh)*36];
            #pragma unroll
            for (int kw = 0; kw < 8; kw++) {
                int k = ci*64 + kh*8 + kw;
                float4 wv = *(const float4*)&w_s[k*C1_WPAD + oc0];
                #pragma unroll
                for (int j = 0; j < 4; j++) {
                    float xv = xr[(sx0 + j)*4 + kw];
                    acc[0][j] += wv.x * xv;
                    acc[1][j] += wv.y * xv;
                    acc[2][j] += wv.z * xv;
                    acc[3][j] += wv.w * xv;
                }
            }
        }
    }

    #pragma unroll
    for (int i = 0; i < 4; i++) {
        int oc = oc0 + i;
        float bias = __ldg(&b1[oc]);
        #pragma unroll
        for (int j = 0; j < 4; j++) {
            float v = acc[i][j] + bias;
            v = v > 0.f ? v : 0.f;
            g_z1[((b*64 + oc)*H1OUT + oh0 + sy)*H1OUT + ow0 + sx0 + j] = v;
        }
    }
}

// ---------------------------------------------------------------------------
// conv2: g_z1[128,64,48,48] * w2[128,64,6,6] s3 p2 -> relu -> g_z2[128,128,16,16]
// block: 256 thr, (b, oc-tile of 64, 8x8 spatial tile), ci chunked by 8
// ---------------------------------------------------------------------------
#define C2_WPAD 68
#define C2_SMEM ((288*C2_WPAD + 8*27*27)*4)

__global__ __launch_bounds__(256) void conv2_kernel(
    const float* __restrict__ w2, const float* __restrict__ b2)
{
    extern __shared__ float sm[];
    float* w_s = sm;                       // 288*68
    float* x_s = sm + 288*C2_WPAD;         // 8*27*27

    const int sp  = blockIdx.x;            // 0..3
    const int ocb = blockIdx.y * 64;       // 0 or 64
    const int b   = blockIdx.z;
    const int oh0 = (sp >> 1) * 8;
    const int ow0 = (sp & 1) * 8;
    const int ih0 = oh0*3 - 2;
    const int iw0 = ow0*3 - 2;
    const int t   = threadIdx.x;

    const int oc0 = (t >> 4) * 4;
    const int sg  = t & 15;
    const int sy  = sg >> 1;
    const int sx0 = (sg & 1) * 4;

    float acc[4][4];
    #pragma unroll
    for (int i = 0; i < 4; i++)
        #pragma unroll
        for (int j = 0; j < 4; j++) acc[i][j] = 0.f;

    for (int cc = 0; cc < 8; cc++) {       // ci chunk of 8
        __syncthreads();
        for (int idx = t; idx < 64*288; idx += 256) {
            int oc = idx / 288, k = idx % 288;
            w_s[k*C2_WPAD + oc] = w2[(ocb + oc)*2304 + cc*288 + k];
        }
        for (int idx = t; idx < 8*27*27; idx += 256) {
            int c = idx / 729, rem = idx % 729;
            int py = rem / 27, px = rem % 27;
            int ih = ih0 + py, iw = iw0 + px;
            float v = 0.f;
            if (ih >= 0 && ih < 48 && iw >= 0 && iw < 48)
                v = g_z1[((b*64 + cc*8 + c)*48 + ih)*48 + iw];
            x_s[idx] = v;
        }
        __syncthreads();

        for (int c = 0; c < 8; c++) {
            #pragma unroll 2
            for (int kh = 0; kh < 6; kh++) {
                const float* xr = &x_s[(c*27 + sy*3 + kh)*27];
                #pragma unroll
                for (int kw = 0; kw < 6; kw++) {
                    int k = c*36 + kh*6 + kw;
                    float4 wv = *(const float4*)&w_s[k*C2_WPAD + oc0];
                    #pragma unroll
                    for (int j = 0; j < 4; j++) {
                        float xv = xr[(sx0 + j)*3 + kw];
                        acc[0][j] += wv.x * xv;
                        acc[1][j] += wv.y * xv;
                        acc[2][j] += wv.z * xv;
                        acc[3][j] += wv.w * xv;
                    }
                }
            }
        }
    }

    #pragma unroll
    for (int i = 0; i < 4; i++) {
        int oc = ocb + oc0 + i;
        float bias = __ldg(&b2[oc]);
        #pragma unroll
        for (int j = 0; j < 4; j++) {
            float v = acc[i][j] + bias;
            v = v > 0.f ? v : 0.f;
            g_z2[((b*128 + oc)*H2OUT + oh0 + sy)*H2OUT + ow0 + sx0 + j] = v;
        }
    }
}

// ---------------------------------------------------------------------------
// conv3: g_z2[128,128,16,16] * w3[64,128,4,4] s1 p0 -> g_z3t[row=b*169+s][64]
// block per batch b, 192 thr (169 active), each active thread = 1 spatial pos,
// 64 accumulators; ci chunked by 16.
// ---------------------------------------------------------------------------
#define C3_WPAD 68
#define C3_SMEM ((256*C3_WPAD + 16*256)*4)

__global__ __launch_bounds__(192) void conv3_kernel(
    const float* __restrict__ w3, const float* __restrict__ b3)
{
    extern __shared__ float sm[];
    float* w_s = sm;                       // 256*68
    float* x_s = sm + 256*C3_WPAD;         // 16*16*16

    const int b = blockIdx.x;
    const int t = threadIdx.x;

    float acc[64];
    #pragma unroll
    for (int o = 0; o < 64; o++) acc[o] = 0.f;

    const int oh = t / 13;
    const int ow = t % 13;

    for (int cc = 0; cc < 8; cc++) {       // ci chunk of 16
        __syncthreads();
        for (int idx = t; idx < 64*256; idx += 192) {
            int oc = idx / 256, k = idx % 256;
            w_s[k*C3_WPAD + oc] = w3[oc*2048 + cc*256 + k];
        }
        for (int idx = t; idx < 16*256; idx += 192)
            x_s[idx] = g_z2[b*128*256 + cc*16*256 + idx];
        __syncthreads();

        if (t < 169) {
            for (int c = 0; c < 16; c++) {
                #pragma unroll
                for (int kh = 0; kh < 4; kh++) {
                    #pragma unroll
                    for (int kw = 0; kw < 4; kw++) {
                        float xv = x_s[(c*16 + oh + kh)*16 + ow + kw];
                        const float4* wp =
                            (const float4*)&w_s[(c*16 + kh*4 + kw)*C3_WPAD];
                        #pragma unroll
                        for (int o = 0; o < 16; o++) {
                            float4 wv = wp[o];
                            acc[4*o + 0] += wv.x * xv;
                            acc[4*o + 1] += wv.y * xv;
                            acc[4*o + 2] += wv.z * xv;
                            acc[4*o + 3] += wv.w * xv;
                        }
                    }
                }
            }
        }
    }

    if (t < 169) {
        float* zo = &g_z3t[(b*HW3 + t)*EMB];
        #pragma unroll
        for (int o = 0; o < 64; o++)
            zo[o] = acc[o] + __ldg(&b3[o]);
    }
}

// ---------------------------------------------------------------------------
// VQ argmin: for each row (21632), argmin_k ||c_k||^2 - 2 z.c_k
// block per batch b, 192 thr (169 active). Full codebook in smem (131 KB).
// ---------------------------------------------------------------------------
#define VQ_SMEM ((NEMB*EMB + NEMB)*4)

__global__ __launch_bounds__(192) void vq_kernel(const float* __restrict__ cb)
{
    extern __shared__ float sm[];
    float* cb_s    = sm;                   // 512*64
    float* cnorm_s = sm + NEMB*EMB;        // 512

    const int b = blockIdx.x;
    const int t = threadIdx.x;

    for (int idx = t; idx < NEMB*EMB; idx += 192)
        cb_s[idx] = cb[idx];
    __syncthreads();
    for (int k = t; k < NEMB; k += 192) {
        float s = 0.f;
        const float* cp = &cb_s[k*EMB];
        #pragma unroll 8
        for (int j = 0; j < EMB; j++) s += cp[j]*cp[j];
        cnorm_s[k] = s;
    }
    __syncthreads();

    if (t >= 169) return;
    const int row = b*HW3 + t;

    float4 zq[16];
    const float4* zp = (const float4*)&g_z3t[row*EMB];
    #pragma unroll
    for (int i = 0; i < 16; i++) zq[i] = zp[i];

    float best = 3.402823466e38f;
    int bi = 0;
    for (int k = 0; k < NEMB; k++) {
        const float4* cp = (const float4*)&cb_s[k*EMB];
        float d0 = 0.f, d1 = 0.f, d2 = 0.f, d3 = 0.f;
        #pragma unroll
        for (int i = 0; i < 16; i++) {
            float4 c = cp[i];
            d0 += zq[i].x * c.x;
            d1 += zq[i].y * c.y;
            d2 += zq[i].z * c.z;
            d3 += zq[i].w * c.w;
        }
        float score = cnorm_s[k] - 2.f*((d0 + d1) + (d2 + d3));
        if (score < best) { best = score; bi = k; }
    }
    g_idx[row] = bi;
}

// ---------------------------------------------------------------------------
// one-hot scatter: out[b][k][hw] = (idx[b][hw] == k)
// ---------------------------------------------------------------------------
__global__ __launch_bounds__(192) void onehot_kernel(float* __restrict__ out)
{
    const int bk = blockIdx.x;             // b*512 + k
    const int t  = threadIdx.x;
    if (t >= HW3) return;
    const int b = bk >> 9;
    const int k = bk & 511;
    out[(size_t)bk * HW3 + t] = (g_idx[b*HW3 + t] == k) ? 1.0f : 0.0f;
}

// ---------------------------------------------------------------------------
extern "C" void kernel_launch(void* const* d_in, const int* in_sizes, int n_in,
                              void* d_out, int out_size)
{
    const float* x  = (const float*)d_in[0];
    const float* w1 = (const float*)d_in[1];
    const float* b1 = (const float*)d_in[2];
    const float* w2 = (const float*)d_in[3];
    const float* b2 = (const float*)d_in[4];
    const float* w3 = (const float*)d_in[5];
    const float* b3 = (const float*)d_in[6];
    const float* cb = (const float*)d_in[7];
    float* out = (float*)d_out;

    cudaFuncSetAttribute(conv1_kernel, cudaFuncAttributeMaxDynamicSharedMemorySize, C1_SMEM);
    cudaFuncSetAttribute(conv2_kernel, cudaFuncAttributeMaxDynamicSharedMemorySize, C2_SMEM);
    cudaFuncSetAttribute(conv3_kernel, cudaFuncAttributeMaxDynamicSharedMemorySize, C3_SMEM);
    cudaFuncSetAttribute(vq_kernel,    cudaFuncAttributeMaxDynamicSharedMemorySize, VQ_SMEM);

    conv1_kernel<<<dim3(36, B_), 256, C1_SMEM>>>(x, w1, b1);
    conv2_kernel<<<dim3(4, 2, B_), 256, C2_SMEM>>>(w2, b2);
    conv3_kernel<<<B_, 192, C3_SMEM>>>(w3, b3);
    vq_kernel<<<B_, 192, VQ_SMEM>>>(cb);
    onehot_kernel<<<B_*NEMB, 192>>>(out);
}